// round 10
// baseline (speedup 1.0000x reference)
#include <cuda_runtime.h>
#include <cuda_fp16.h>
#include <cstdint>

// Problem dims
static constexpr int M = 256;
static constexpr int K = 4096;
static constexpr int N = 8192;
static constexpr int KITERS = K / 64;     // 64 K-chunks of 64
static constexpr int THREADS = 512;

// SMEM layout (per 512-thread CTA, tile 256x64):
//  [0,1024)             header (unused, alignment)
//  [1024, +3*32768)     A fragment ring: 3 stages x 32KB (16 mi x 4 ks x 32 lanes x 16B)
//  [99328, +2*8192)     B dequant double buffer (64 rows x 128B each)
static constexpr int SMEM_A = 1024;
static constexpr int SMEM_B = 1024 + 3 * 32768;       // 99328
static constexpr int SMEM_TOTAL = SMEM_B + 2 * 8192;  // 115712

// A in m16n8k16 fragment layout, fp16, built by convert kernel.
// Index: ((mi * (K/16) + ki) * 32 + lane) -> uint4 (regs a0,a1,a2,a3)
__device__ uint4 g_xa[(M / 16) * (K / 16) * 32];

// ---------------- helpers ----------------

__device__ __forceinline__ uint32_t smem_u32(const void* p) {
    uint32_t a;
    asm("{ .reg .u64 t; cvta.to.shared.u64 t, %1; cvt.u32.u64 %0, t; }"
        : "=r"(a) : "l"(p));
    return a;
}

__device__ __forceinline__ uint32_t sw128(uint32_t off) {
    return off ^ ((off >> 3) & 0x70);
}

// Dequant HALF of a 16-weight group (2 int32, low byte each = 4 x 2-bit codes)
// into 4 u32 = 8 fp16, via a 4-entry fp16 LUT + PRMT byte gather.
__device__ __forceinline__ void dequant8(const int2& p2, float n, uint32_t o[4]) {
    uint32_t b1 = (uint32_t)__half_as_ushort(__float2half_rn(n));
    uint32_t b3 = (uint32_t)__half_as_ushort(__float2half_rn(n * (1.0f / 3.0f)));
    uint32_t loT = (b1 ^ 0x8000u) | ((b3 ^ 0x8000u) << 16);  // bytes: [-n][-n/3]
    uint32_t hiT = b3 | (b1 << 16);                          // bytes: [n/3][n]
    uint32_t pv[2] = { (uint32_t)p2.x, (uint32_t)p2.y };
    #pragma unroll
    for (int q = 0; q < 2; ++q) {
        uint32_t by = pv[q] & 0xFFu;   // 4 x 2-bit codes
        uint32_t l = by & 0xFu;
        uint32_t h = by >> 4;
        uint32_t c0 = (l & 3u) * 0x22u + (l & 0xCu) * 0x880u + 0x1010u;
        uint32_t c1 = (h & 3u) * 0x22u + (h & 0xCu) * 0x880u + 0x1010u;
        o[2 * q]     = __byte_perm(loT, hiT, c0);
        o[2 * q + 1] = __byte_perm(loT, hiT, c1);
    }
}

// ---------------- kernel 0: x fp32 -> A-fragment fp16 layout ----------------

__global__ void convert_x_frag(const float* __restrict__ x) {
    int g = blockIdx.x * blockDim.x + threadIdx.x;   // 0 .. 131071
    int lane = g & 31;
    int ki = (g >> 5) & (K / 16 - 1);
    int mi = g >> 13;
    int r = lane >> 2;
    int c = (lane & 3) * 2;
    const float* base = x + (size_t)(mi * 16 + r) * K + ki * 16 + c;
    float2 v00 = *reinterpret_cast<const float2*>(base);
    float2 v10 = *reinterpret_cast<const float2*>(base + 8 * K);
    float2 v01 = *reinterpret_cast<const float2*>(base + 8);
    float2 v11 = *reinterpret_cast<const float2*>(base + 8 * K + 8);
    uint4 o;
    o.x = (uint32_t)__half_as_ushort(__float2half_rn(v00.x)) |
          ((uint32_t)__half_as_ushort(__float2half_rn(v00.y)) << 16);
    o.y = (uint32_t)__half_as_ushort(__float2half_rn(v10.x)) |
          ((uint32_t)__half_as_ushort(__float2half_rn(v10.y)) << 16);
    o.z = (uint32_t)__half_as_ushort(__float2half_rn(v01.x)) |
          ((uint32_t)__half_as_ushort(__float2half_rn(v01.y)) << 16);
    o.w = (uint32_t)__half_as_ushort(__float2half_rn(v11.x)) |
          ((uint32_t)__half_as_ushort(__float2half_rn(v11.y)) << 16);
    g_xa[g] = o;
}

// ---------------- kernel 1: fused dequant + fp16 HMMA GEMM ----------------
// Grid (128, 1): blockIdx.x = N-tile (64 cols). CTA tile = 256(M) x 64(N).
// 512 threads = 16 warps as 4(M) x 4(N); warp tile 64x16 (mt=4, nt=2).
// Each weight group is dequantized exactly ONCE across the whole grid;
// two threads split each group (one LDG.64 + 4 PRMT each).
// A: cp.async gmem->SMEM ring (3 stages x 32KB, issued 2 iters ahead).
// B: packed LDG 1 iter ahead -> dequant -> SMEM (SW128) -> ldmatrix, 2 buffers.

__global__ void __launch_bounds__(THREADS, 1)
linear2bit_gemm(const int4* __restrict__ wq,        // one int4 = one 16-value group
                const void* __restrict__ wn_raw,    // [NUM_GROUPS] norms (fp32 or fp16)
                const float* __restrict__ bias,     // [N]
                float* __restrict__ out)            // [M, N]
{
    extern __shared__ char smem[];
    const uint32_t sb = smem_u32(smem);
    const int tid = threadIdx.x;
    const int wid = tid >> 5;
    const int lid = tid & 31;
    const int ntile = blockIdx.x;                   // 64-col tile

    // ---- runtime dtype probe for weight_norm ----
    const float* wnf = (const float*)wn_raw;
    const __half* wnh = (const __half*)wn_raw;
    const float probe = __ldg(wnf);
    const bool norm_f32 = (probe > 6e-5f && probe < 0.06f);

    const int warp_m = wid >> 2;     // 4 x 64 rows
    const int warp_n = wid & 3;      // 4 x 16 cols

    // B ldmatrix per-lane unswizzled base (one 16-row group per warp)
    const uint32_t brow =
        (uint32_t)((warp_n * 16 + (lid & 15)) * 128 + (lid >> 4) * 16);

    // ---- A cp.async: thread tid copies 4 uint4 chunks per iter (32KB) ----
    // flat = tid + 512*j (j=0..3); q = flat>>5 = mi*4+ks (mi 0..15); lane = flat&31
    const uint4* abase = g_xa;
    auto cp_a = [&](int it, int slot) {
        uint32_t sdst = sb + SMEM_A + (uint32_t)slot * 32768u + (uint32_t)tid * 16u;
        #pragma unroll
        for (int j = 0; j < 4; ++j) {
            int flat = tid + THREADS * j;
            int lane = flat & 31;
            int q = flat >> 5;              // mi*4 + ks
            int mi = q >> 2;
            int ks = q & 3;
            const uint4* src = abase + ((size_t)mi * (K / 16) + it * 4 + ks) * 32 + lane;
            asm volatile("cp.async.cg.shared.global [%0], [%1], 16;"
                         :: "r"(sdst + (uint32_t)j * 8192u), "l"(src) : "memory");
        }
        asm volatile("cp.async.commit_group;" ::: "memory");
    };

    // A LDS byte base within a slot for this warp/lane:
    // chunk index = (warp_m*4 + mt)*4 + ks, each chunk 32 lanes x 16B
    const uint32_t a_lds_off = (uint32_t)((warp_m * 4 * 4) * 32 + lid) * 16u;

    float acc[4][2][4];
    #pragma unroll
    for (int mt = 0; mt < 4; ++mt)
        #pragma unroll
        for (int nt = 0; nt < 2; ++nt)
            #pragma unroll
            for (int e = 0; e < 4; ++e) acc[mt][nt][e] = 0.0f;

    // B staging: half a group per thread per iter (256 groups, 512 threads)
    const int bgi  = tid >> 1;      // group index 0..255
    const int bhalf = tid & 1;      // which 8 weights of the group
    const int br = bgi >> 2;        // B row in tile (0..63)
    const int bj = bgi & 3;         // group within K-chunk (0..3)
    const int bg_base = (ntile * 64 + br) * 256 + bj;   // + it*4

    int2  bv;
    float bn;

    auto ldg_b = [&](int it) {
        int gidx = bg_base + it * 4;
        bv = __ldg(reinterpret_cast<const int2*>(wq + gidx) + bhalf);
        bn = norm_f32 ? __ldg(wnf + gidx) : __half2float(__ldg(wnh + gidx));
    };
    auto sts_b = [&](int b) {
        char* bbuf = smem + SMEM_B + b * 8192;
        uint32_t o[4];
        dequant8(bv, bn, o);
        uint32_t off = (uint32_t)(br * 128 + bj * 32 + bhalf * 16);
        *reinterpret_cast<int4*>(bbuf + sw128(off)) =
            make_int4((int)o[0], (int)o[1], (int)o[2], (int)o[3]);
    };

    // ---- prologue ----
    ldg_b(0);
    cp_a(0, 0);
    cp_a(1, 1);
    sts_b(0);
    asm volatile("cp.async.wait_group 1;" ::: "memory");   // slot 0 ready
    __syncthreads();

    #pragma unroll 1
    for (int it = 0; it < KITERS; ++it) {
        const int b = it & 1;
        if (it + 1 < KITERS) ldg_b(it + 1);

        const char* aslot = smem + SMEM_A + (it % 3) * 32768 + a_lds_off;
        const uint32_t bb = sb + SMEM_B + (uint32_t)b * 8192u;

        #pragma unroll
        for (int ks = 0; ks < 4; ++ks) {
            const uint32_t kb = (uint32_t)(ks * 32);   // 16 halves per k-step

            // A fragments for this ks: 4 x LDS.128 (mt = 0..3)
            uint4 af[4];
            #pragma unroll
            for (int mt = 0; mt < 4; ++mt)
                af[mt] = *reinterpret_cast<const uint4*>(
                    aslot + (mt * 4 + ks) * 32 * 16);

            // B fragments: one ldmatrix.x4 covers n16 x k16
            uint32_t bf[4];
            {
                uint32_t addr = bb + sw128(brow + kb);
                asm volatile(
                    "ldmatrix.sync.aligned.m8n8.x4.shared.b16 {%0,%1,%2,%3}, [%4];"
                    : "=r"(bf[0]), "=r"(bf[1]), "=r"(bf[2]), "=r"(bf[3])
                    : "r"(addr));
            }
            #pragma unroll
            for (int mt = 0; mt < 4; ++mt) {
                #pragma unroll
                for (int nt = 0; nt < 2; ++nt) {
                    asm volatile(
                        "mma.sync.aligned.m16n8k16.row.col.f32.f16.f16.f32 "
                        "{%0,%1,%2,%3}, {%4,%5,%6,%7}, {%8,%9}, {%0,%1,%2,%3};"
                        : "+f"(acc[mt][nt][0]), "+f"(acc[mt][nt][1]),
                          "+f"(acc[mt][nt][2]), "+f"(acc[mt][nt][3])
                        : "r"(af[mt].x), "r"(af[mt].y),
                          "r"(af[mt].z), "r"(af[mt].w),
                          "r"(bf[nt]), "r"(bf[nt + 2]));
                }
            }
        }

        if (it + 1 < KITERS) sts_b(b ^ 1);

        // Issue A copy for it+2 (clamped at tail; slot clobber is safe:
        // (it+2)%3 == (it-1)%3 which was already consumed).
        int itp = it + 2 < KITERS ? it + 2 : KITERS - 1;
        cp_a(itp, (it + 2) % 3);
        asm volatile("cp.async.wait_group 1;" ::: "memory");   // slot (it+1) ready
        __syncthreads();
    }

    // ---- epilogue: write accumulators + bias ----
    {
        const int mbase = warp_m * 64;
        const int nbase = ntile * 64 + warp_n * 16;
        const int rq = lid >> 2;             // row within m16 (0..7)
        const int cq = (lid & 3) * 2;        // col within n8 (0,2,4,6)
        #pragma unroll
        for (int mt = 0; mt < 4; ++mt) {
            #pragma unroll
            for (int nt = 0; nt < 2; ++nt) {
                int m0 = mbase + mt * 16 + rq;
                int n0 = nbase + nt * 8 + cq;
                float2 bsv = __ldg(reinterpret_cast<const float2*>(bias + n0));
                float2 v0, v1;
                v0.x = acc[mt][nt][0] + bsv.x;
                v0.y = acc[mt][nt][1] + bsv.y;
                v1.x = acc[mt][nt][2] + bsv.x;
                v1.y = acc[mt][nt][3] + bsv.y;
                *reinterpret_cast<float2*>(out + (size_t)m0 * N + n0) = v0;
                *reinterpret_cast<float2*>(out + (size_t)(m0 + 8) * N + n0) = v1;
            }
        }
    }
}

// ---------------- launch ----------------

extern "C" void kernel_launch(void* const* d_in, const int* in_sizes, int n_in,
                              void* d_out, int out_size) {
    (void)in_sizes; (void)n_in; (void)out_size;
    const float* x    = (const float*)d_in[0];
    const int4*  wq   = (const int4*)d_in[1];    // [NUM_GROUPS] groups of 4 int32
    const void*  wn   = (const void*)d_in[2];    // [NUM_GROUPS] norms
    const float* bias = (const float*)d_in[3];
    float*       out  = (float*)d_out;

    cudaFuncSetAttribute(linear2bit_gemm,
                         cudaFuncAttributeMaxDynamicSharedMemorySize, SMEM_TOTAL);

    convert_x_frag<<<(M / 16) * (K / 16) * 32 / 256, 256>>>(x);
    linear2bit_gemm<<<N / 64, THREADS, SMEM_TOTAL>>>(wq, wn, bias, out);
}

// round 12
// speedup vs baseline: 1.1204x; 1.1204x over previous
#include <cuda_runtime.h>
#include <cuda_fp16.h>
#include <cstdint>

// Problem dims
static constexpr int M = 256;
static constexpr int K = 4096;
static constexpr int N = 8192;
static constexpr int SITERS = K / 128;    // 32 super-iters of BK=128
static constexpr int THREADS = 512;       // 16 warps: 4(M) x 2(N) x 2(K-team)

// SMEM layout (per 512-thread CTA, tile 256x64, BK=128):
//  [0,1024)              header (alignment)
//  [1024, +3*65536)      A fragment ring: 3 stages x 64KB
//                        stage = [kc(2)][mi(16)][ks(4)][lane(32)] x 16B
//  [197632, +2*16384)    B double buffer: per buffer 2 k-chunks x (64 rows x 128B)
static constexpr int SMEM_A = 1024;
static constexpr int SMEM_B = 1024 + 3 * 65536;        // 197632
static constexpr int SMEM_TOTAL = SMEM_B + 2 * 16384;  // 230400

// A in m16n8k16 fragment layout, fp16, built by convert kernel.
// Index: ((mi * (K/16) + ki) * 32 + lane) -> uint4 (regs a0,a1,a2,a3)
__device__ uint4 g_xa[(M / 16) * (K / 16) * 32];

// ---------------- helpers ----------------

__device__ __forceinline__ uint32_t smem_u32(const void* p) {
    uint32_t a;
    asm("{ .reg .u64 t; cvta.to.shared.u64 t, %1; cvt.u32.u64 %0, t; }"
        : "=r"(a) : "l"(p));
    return a;
}

__device__ __forceinline__ uint32_t sw128(uint32_t off) {
    return off ^ ((off >> 3) & 0x70);
}

// Dequant one 16-weight group (4 int32, low byte each = 4 x 2-bit codes)
// into 8 u32 = 16 fp16, via a 4-entry fp16 LUT + PRMT byte gather.
__device__ __forceinline__ void dequant16(const int4& p4, float n, uint32_t o[8]) {
    uint32_t b1 = (uint32_t)__half_as_ushort(__float2half_rn(n));
    uint32_t b3 = (uint32_t)__half_as_ushort(__float2half_rn(n * (1.0f / 3.0f)));
    uint32_t loT = (b1 ^ 0x8000u) | ((b3 ^ 0x8000u) << 16);  // bytes: [-n][-n/3]
    uint32_t hiT = b3 | (b1 << 16);                          // bytes: [n/3][n]
    uint32_t pv[4] = { (uint32_t)p4.x, (uint32_t)p4.y, (uint32_t)p4.z, (uint32_t)p4.w };
    #pragma unroll
    for (int q = 0; q < 4; ++q) {
        uint32_t by = pv[q] & 0xFFu;   // 4 x 2-bit codes
        uint32_t l = by & 0xFu;
        uint32_t h = by >> 4;
        uint32_t c0 = (l & 3u) * 0x22u + (l & 0xCu) * 0x880u + 0x1010u;
        uint32_t c1 = (h & 3u) * 0x22u + (h & 0xCu) * 0x880u + 0x1010u;
        o[2 * q]     = __byte_perm(loT, hiT, c0);
        o[2 * q + 1] = __byte_perm(loT, hiT, c1);
    }
}

// ---------------- kernel 0: x fp32 -> A-fragment fp16 layout ----------------

__global__ void convert_x_frag(const float* __restrict__ x) {
    int g = blockIdx.x * blockDim.x + threadIdx.x;   // 0 .. 131071
    int lane = g & 31;
    int ki = (g >> 5) & (K / 16 - 1);
    int mi = g >> 13;
    int r = lane >> 2;
    int c = (lane & 3) * 2;
    const float* base = x + (size_t)(mi * 16 + r) * K + ki * 16 + c;
    float2 v00 = *reinterpret_cast<const float2*>(base);
    float2 v10 = *reinterpret_cast<const float2*>(base + 8 * K);
    float2 v01 = *reinterpret_cast<const float2*>(base + 8);
    float2 v11 = *reinterpret_cast<const float2*>(base + 8 * K + 8);
    uint4 o;
    o.x = (uint32_t)__half_as_ushort(__float2half_rn(v00.x)) |
          ((uint32_t)__half_as_ushort(__float2half_rn(v00.y)) << 16);
    o.y = (uint32_t)__half_as_ushort(__float2half_rn(v10.x)) |
          ((uint32_t)__half_as_ushort(__float2half_rn(v10.y)) << 16);
    o.z = (uint32_t)__half_as_ushort(__float2half_rn(v01.x)) |
          ((uint32_t)__half_as_ushort(__float2half_rn(v01.y)) << 16);
    o.w = (uint32_t)__half_as_ushort(__float2half_rn(v11.x)) |
          ((uint32_t)__half_as_ushort(__float2half_rn(v11.y)) << 16);
    g_xa[g] = o;
}

// ---------------- kernel 1: fused dequant + fp16 HMMA GEMM, warp split-K ----
// Grid (128): blockIdx.x = N-tile (64 cols). CTA tile = 256(M) x 64(N), BK=128.
// 16 warps: team = (wid>>2)&1 handles k-chunk [team*64, team*64+64) of each
// super-iter; within a team 8 warps as 4(M) x 2(N), warp tile 64x32.
// Each weight group dequantized exactly once across the whole grid.
// A: cp.async ring (3 stages x 64KB, 2 super-iters ahead), 1 sync per iter.
// End: drain cp.async (ring is reused!), team-1 accs -> smem -> team 0 adds.

__global__ void __launch_bounds__(THREADS, 1)
linear2bit_gemm(const int4* __restrict__ wq,        // one int4 = one 16-value group
                const void* __restrict__ wn_raw,    // [NUM_GROUPS] norms (fp32 or fp16)
                const float* __restrict__ bias,     // [N]
                float* __restrict__ out)            // [M, N]
{
    extern __shared__ char smem[];
    const uint32_t sb = smem_u32(smem);
    const int tid = threadIdx.x;
    const int wid = tid >> 5;
    const int lid = tid & 31;
    const int ntile = blockIdx.x;                   // 64-col tile

    // ---- runtime dtype probe for weight_norm ----
    const float* wnf = (const float*)wn_raw;
    const __half* wnh = (const __half*)wn_raw;
    const float probe = __ldg(wnf);
    const bool norm_f32 = (probe > 6e-5f && probe < 0.06f);

    // team / compute-warp decomposition (teams interleaved across SMSPs)
    const int team = (wid >> 2) & 1;                       // k-chunk owner
    const int cwid = (wid & 3) | ((wid >> 3) << 2);        // 0..7 within team
    const int warp_m = cwid >> 1;    // 4 x 64 rows
    const int warp_n = cwid & 1;     // 2 x 32 cols

    // B ldmatrix per-lane unswizzled bases (two 16-row groups per warp)
    uint32_t brow[2];
    #pragma unroll
    for (int p = 0; p < 2; ++p)
        brow[p] = (uint32_t)((warp_n * 32 + p * 16 + (lid & 15)) * 128 + (lid >> 4) * 16);

    // ---- A cp.async: thread copies 8 x 16B chunks per super-iter (64KB) ----
    // chunk flat = tid + 512*j ; decompose flat>>5 = (kc*16 + mi)*4 + ks
    auto cp_a = [&](int si, int slot) {
        uint32_t sdst = sb + SMEM_A + (uint32_t)slot * 65536u + (uint32_t)tid * 16u;
        #pragma unroll
        for (int j = 0; j < 8; ++j) {
            int flat = tid + THREADS * j;
            int lane = flat & 31;
            int t = flat >> 5;              // (kc*16 + mi)*4 + ks
            int ks = t & 3;
            int mi = (t >> 2) & 15;
            int kc = t >> 6;
            const uint4* src = g_xa + ((size_t)mi * (K / 16) + si * 8 + kc * 4 + ks) * 32 + lane;
            asm volatile("cp.async.cg.shared.global [%0], [%1], 16;"
                         :: "r"(sdst + (uint32_t)j * 8192u), "l"(src) : "memory");
        }
        asm volatile("cp.async.commit_group;" ::: "memory");
    };

    // A LDS byte base within a stage for this warp/lane (team half + warp rows)
    const uint32_t a_lds_off =
        (uint32_t)team * 32768u + (uint32_t)((warp_m * 4 * 4) * 32 + lid) * 16u;

    float acc[4][4][4];
    #pragma unroll
    for (int mt = 0; mt < 4; ++mt)
        #pragma unroll
        for (int nt = 0; nt < 4; ++nt)
            #pragma unroll
            for (int e = 0; e < 4; ++e) acc[mt][nt][e] = 0.0f;

    // B staging: 1 group per thread per super-iter (64 rows x 8 groups = 512)
    const int br = tid >> 3;        // B row in tile (0..63)
    const int bj = tid & 7;         // group within K-super-chunk (0..7)
    const int bg_base = (ntile * 64 + br) * 256 + bj;   // + si*8

    int4  bv;
    float bn;

    auto ldg_b = [&](int si) {
        int gidx = bg_base + si * 8;
        bv = __ldg(wq + gidx);
        bn = norm_f32 ? __ldg(wnf + gidx) : __half2float(__ldg(wnh + gidx));
    };
    auto sts_b = [&](int b) {
        char* bbuf = smem + SMEM_B + b * 16384 + (bj >> 2) * 8192;
        uint32_t o[8];
        dequant16(bv, bn, o);
        uint32_t off = (uint32_t)(br * 128 + (bj & 3) * 32);
        *reinterpret_cast<int4*>(bbuf + sw128(off)) =
            make_int4((int)o[0], (int)o[1], (int)o[2], (int)o[3]);
        *reinterpret_cast<int4*>(bbuf + sw128(off + 16)) =
            make_int4((int)o[4], (int)o[5], (int)o[6], (int)o[7]);
    };

    // ---- prologue ----
    ldg_b(0);
    cp_a(0, 0);
    cp_a(1, 1);
    sts_b(0);
    asm volatile("cp.async.wait_group 1;" ::: "memory");   // stage 0 ready
    __syncthreads();

    #pragma unroll 1
    for (int si = 0; si < SITERS; ++si) {
        const int b = si & 1;
        if (si + 1 < SITERS) ldg_b(si + 1);

        const char* aslot = smem + SMEM_A + (si % 3) * 65536 + a_lds_off;
        const uint32_t bb = sb + SMEM_B + (uint32_t)b * 16384u + (uint32_t)team * 8192u;

        #pragma unroll
        for (int ks = 0; ks < 4; ++ks) {
            const uint32_t kb = (uint32_t)(ks * 32);   // 16 halves per k-step

            // A fragments for this ks: 4 x LDS.128 (mt = 0..3)
            uint4 af[4];
            #pragma unroll
            for (int mt = 0; mt < 4; ++mt)
                af[mt] = *reinterpret_cast<const uint4*>(
                    aslot + (mt * 4 + ks) * 32 * 16);

            uint32_t bf[2][4];
            #pragma unroll
            for (int p = 0; p < 2; ++p) {
                uint32_t addr = bb + sw128(brow[p] + kb);
                asm volatile(
                    "ldmatrix.sync.aligned.m8n8.x4.shared.b16 {%0,%1,%2,%3}, [%4];"
                    : "=r"(bf[p][0]), "=r"(bf[p][1]), "=r"(bf[p][2]), "=r"(bf[p][3])
                    : "r"(addr));
            }
            #pragma unroll
            for (int mt = 0; mt < 4; ++mt) {
                #pragma unroll
                for (int nt = 0; nt < 4; ++nt) {
                    uint32_t b0 = bf[nt >> 1][nt & 1];
                    uint32_t b1 = bf[nt >> 1][(nt & 1) + 2];
                    asm volatile(
                        "mma.sync.aligned.m16n8k16.row.col.f32.f16.f16.f32 "
                        "{%0,%1,%2,%3}, {%4,%5,%6,%7}, {%8,%9}, {%0,%1,%2,%3};"
                        : "+f"(acc[mt][nt][0]), "+f"(acc[mt][nt][1]),
                          "+f"(acc[mt][nt][2]), "+f"(acc[mt][nt][3])
                        : "r"(af[mt].x), "r"(af[mt].y),
                          "r"(af[mt].z), "r"(af[mt].w),
                          "r"(b0), "r"(b1));
                }
            }
        }

        if (si + 1 < SITERS) sts_b(b ^ 1);

        // Issue A copy for si+2 (clamped at tail; 3-stage ring: slot
        // (si+2)%3 == (si-1)%3 which was consumed before the last sync).
        int sip = si + 2 < SITERS ? si + 2 : SITERS - 1;
        cp_a(sip, (si + 2) % 3);
        asm volatile("cp.async.wait_group 1;" ::: "memory");   // stage si+1 ready
        __syncthreads();
    }

    // ---- DRAIN the async pipe before reusing the A ring for the reduction.
    // The tail-clamped cp_a groups may still be writing stage 0's bytes, which
    // alias the reduction scratch below (this was the R11 corruption).
    asm volatile("cp.async.wait_group 0;" ::: "memory");
    __syncthreads();

    // ---- split-K reduction: team 1 -> smem -> team 0 adds ----
    // Reuse the A ring region. Per team-1 warp: 16 float4 chunks laid out
    // [chunk(16)][lane(32)] so loads are conflict-free.
    if (team == 1) {
        char* red = smem + SMEM_A + cwid * 8192 + lid * 16;
        #pragma unroll
        for (int mt = 0; mt < 4; ++mt)
            #pragma unroll
            for (int nt = 0; nt < 4; ++nt)
                *reinterpret_cast<float4*>(red + (mt * 4 + nt) * 512) =
                    make_float4(acc[mt][nt][0], acc[mt][nt][1],
                                acc[mt][nt][2], acc[mt][nt][3]);
    }
    __syncthreads();

    if (team == 0) {
        const char* red = smem + SMEM_A + cwid * 8192 + lid * 16;
        const int mbase = warp_m * 64;
        const int nbase = ntile * 64 + warp_n * 32;
        const int rq = lid >> 2;             // row within m16 (0..7)
        const int cq = (lid & 3) * 2;        // col within n8 (0,2,4,6)
        #pragma unroll
        for (int mt = 0; mt < 4; ++mt) {
            #pragma unroll
            for (int nt = 0; nt < 4; ++nt) {
                float4 r = *reinterpret_cast<const float4*>(red + (mt * 4 + nt) * 512);
                int m0 = mbase + mt * 16 + rq;
                int n0 = nbase + nt * 8 + cq;
                float2 bsv = __ldg(reinterpret_cast<const float2*>(bias + n0));
                float2 v0, v1;
                v0.x = acc[mt][nt][0] + r.x + bsv.x;
                v0.y = acc[mt][nt][1] + r.y + bsv.y;
                v1.x = acc[mt][nt][2] + r.z + bsv.x;
                v1.y = acc[mt][nt][3] + r.w + bsv.y;
                *reinterpret_cast<float2*>(out + (size_t)m0 * N + n0) = v0;
                *reinterpret_cast<float2*>(out + (size_t)(m0 + 8) * N + n0) = v1;
            }
        }
    }
}

// ---------------- launch ----------------

extern "C" void kernel_launch(void* const* d_in, const int* in_sizes, int n_in,
                              void* d_out, int out_size) {
    (void)in_sizes; (void)n_in; (void)out_size;
    const float* x    = (const float*)d_in[0];
    const int4*  wq   = (const int4*)d_in[1];    // [NUM_GROUPS] groups of 4 int32
    const void*  wn   = (const void*)d_in[2];    // [NUM_GROUPS] norms
    const float* bias = (const float*)d_in[3];
    float*       out  = (float*)d_out;

    cudaFuncSetAttribute(linear2bit_gemm,
                         cudaFuncAttributeMaxDynamicSharedMemorySize, SMEM_TOTAL);

    convert_x_frag<<<(M / 16) * (K / 16) * 32 / 256, 256>>>(x);
    linear2bit_gemm<<<N / 64, THREADS, SMEM_TOTAL>>>(wq, wn, bias, out);
}

// round 13
// speedup vs baseline: 1.1547x; 1.0306x over previous
#include <cuda_runtime.h>
#include <cuda_fp16.h>
#include <cstdint>

// Problem dims
static constexpr int M = 256;
static constexpr int K = 4096;
static constexpr int N = 8192;
static constexpr int SITERS = K / 128;    // 32 super-iters of BK=128
static constexpr int THREADS = 512;       // 16 warps: 4(M) x 2(N) x 2(K-team)

// SMEM layout (per 512-thread CTA, tile 256x64, BK=128):
//  [0,1024)              header (alignment)
//  [1024, +3*65536)      A fragment ring: 3 stages x 64KB
//                        stage = [kc(2)][mi(16)][ks(4)][lane(32)] x 16B
//  [197632, +2*16384)    B double buffer: per buffer 2 k-chunks x (64 rows x 128B)
static constexpr int SMEM_A = 1024;
static constexpr int SMEM_B = 1024 + 3 * 65536;        // 197632
static constexpr int SMEM_TOTAL = SMEM_B + 2 * 16384;  // 230400

// A in m16n8k16 fragment layout, fp16, built by convert kernel.
// Index: ((mi * (K/16) + ki) * 32 + lane) -> uint4 (regs a0,a1,a2,a3)
__device__ uint4 g_xa[(M / 16) * (K / 16) * 32];

// ---------------- helpers ----------------

__device__ __forceinline__ uint32_t smem_u32(const void* p) {
    uint32_t a;
    asm("{ .reg .u64 t; cvta.to.shared.u64 t, %1; cvt.u32.u64 %0, t; }"
        : "=r"(a) : "l"(p));
    return a;
}

__device__ __forceinline__ uint32_t sw128(uint32_t off) {
    return off ^ ((off >> 3) & 0x70);
}

// Dequant one 16-weight group (4 int32, low byte each = 4 x 2-bit codes)
// into 8 u32 = 16 fp16, via a 4-entry fp16 LUT + PRMT byte gather.
__device__ __forceinline__ void dequant16(const int4& p4, float n, uint32_t o[8]) {
    uint32_t b1 = (uint32_t)__half_as_ushort(__float2half_rn(n));
    uint32_t b3 = (uint32_t)__half_as_ushort(__float2half_rn(n * (1.0f / 3.0f)));
    uint32_t loT = (b1 ^ 0x8000u) | ((b3 ^ 0x8000u) << 16);  // bytes: [-n][-n/3]
    uint32_t hiT = b3 | (b1 << 16);                          // bytes: [n/3][n]
    uint32_t pv[4] = { (uint32_t)p4.x, (uint32_t)p4.y, (uint32_t)p4.z, (uint32_t)p4.w };
    #pragma unroll
    for (int q = 0; q < 4; ++q) {
        uint32_t by = pv[q] & 0xFFu;   // 4 x 2-bit codes
        uint32_t l = by & 0xFu;
        uint32_t h = by >> 4;
        uint32_t c0 = (l & 3u) * 0x22u + (l & 0xCu) * 0x880u + 0x1010u;
        uint32_t c1 = (h & 3u) * 0x22u + (h & 0xCu) * 0x880u + 0x1010u;
        o[2 * q]     = __byte_perm(loT, hiT, c0);
        o[2 * q + 1] = __byte_perm(loT, hiT, c1);
    }
}

// ---------------- kernel 0: x fp32 -> A-fragment fp16 layout ----------------

__global__ void convert_x_frag(const float* __restrict__ x) {
    int g = blockIdx.x * blockDim.x + threadIdx.x;   // 0 .. 131071
    int lane = g & 31;
    int ki = (g >> 5) & (K / 16 - 1);
    int mi = g >> 13;
    int r = lane >> 2;
    int c = (lane & 3) * 2;
    const float* base = x + (size_t)(mi * 16 + r) * K + ki * 16 + c;
    float2 v00 = *reinterpret_cast<const float2*>(base);
    float2 v10 = *reinterpret_cast<const float2*>(base + 8 * K);
    float2 v01 = *reinterpret_cast<const float2*>(base + 8);
    float2 v11 = *reinterpret_cast<const float2*>(base + 8 * K + 8);
    uint4 o;
    o.x = (uint32_t)__half_as_ushort(__float2half_rn(v00.x)) |
          ((uint32_t)__half_as_ushort(__float2half_rn(v00.y)) << 16);
    o.y = (uint32_t)__half_as_ushort(__float2half_rn(v10.x)) |
          ((uint32_t)__half_as_ushort(__float2half_rn(v10.y)) << 16);
    o.z = (uint32_t)__half_as_ushort(__float2half_rn(v01.x)) |
          ((uint32_t)__half_as_ushort(__float2half_rn(v01.y)) << 16);
    o.w = (uint32_t)__half_as_ushort(__float2half_rn(v11.x)) |
          ((uint32_t)__half_as_ushort(__float2half_rn(v11.y)) << 16);
    g_xa[g] = o;
}

// ---------------- kernel 1: fused dequant + fp16 HMMA GEMM, warp split-K ----
// Grid (128): blockIdx.x = N-tile (64 cols). CTA tile = 256(M) x 64(N), BK=128.
// 16 warps: team = (wid>>2)&1 handles k-chunk [team*64, team*64+64) of each
// super-iter; within a team 8 warps as 4(M) x 2(N), warp tile 64x32.
// Each weight group dequantized exactly once across the whole grid.
// A: cp.async ring (3 stages x 64KB, 2 super-iters ahead), 1 sync per iter.
// cp.async source addresses strength-reduced: src_j = base(si) + const_j.
// End: drain cp.async (ring is reused!), team-1 accs -> smem -> team 0 adds.

__global__ void __launch_bounds__(THREADS, 1)
linear2bit_gemm(const int4* __restrict__ wq,        // one int4 = one 16-value group
                const void* __restrict__ wn_raw,    // [NUM_GROUPS] norms (fp32 or fp16)
                const float* __restrict__ bias,     // [N]
                float* __restrict__ out)            // [M, N]
{
    extern __shared__ char smem[];
    const uint32_t sb = smem_u32(smem);
    const int tid = threadIdx.x;
    const int wid = tid >> 5;
    const int lid = tid & 31;
    const int ntile = blockIdx.x;                   // 64-col tile

    // ---- runtime dtype probe for weight_norm ----
    const float* wnf = (const float*)wn_raw;
    const __half* wnh = (const __half*)wn_raw;
    const float probe = __ldg(wnf);
    const bool norm_f32 = (probe > 6e-5f && probe < 0.06f);

    // team / compute-warp decomposition (teams interleaved across SMSPs)
    const int team = (wid >> 2) & 1;                       // k-chunk owner
    const int cwid = (wid & 3) | ((wid >> 3) << 2);        // 0..7 within team
    const int warp_m = cwid >> 1;    // 4 x 64 rows
    const int warp_n = cwid & 1;     // 2 x 32 cols

    // B ldmatrix per-lane unswizzled bases (two 16-row groups per warp)
    uint32_t brow[2];
    #pragma unroll
    for (int p = 0; p < 2; ++p)
        brow[p] = (uint32_t)((warp_n * 32 + p * 16 + (lid & 15)) * 128 + (lid >> 4) * 16);

    // ---- A cp.async, strength-reduced addressing ----
    // Original: flat = tid + 512j; t = flat>>5 = wid + 16j;
    //   ks = t&3 = wid&3; mi = ((wid>>2) + 4j)&15; kc = t>>6 = (j>=4).
    // uint4 offset = mi*8192 + si*256 + kc*128 + ks*32 + lane
    //             = si*256 + a_off0 + (j&3)*32768 + (j>>2)*128  (j-terms immediate)
    const uint32_t a_off0 =
        (uint32_t)((wid >> 2) * 8192 + (wid & 3) * 32 + lid);
    auto cp_a = [&](int si, int slot) {
        const uint4* srcb = g_xa + (size_t)si * 256 + a_off0;
        uint32_t sdst = sb + SMEM_A + (uint32_t)slot * 65536u + (uint32_t)tid * 16u;
        #pragma unroll
        for (int j = 0; j < 8; ++j) {
            const uint4* src = srcb + (j & 3) * 32768 + (j >> 2) * 128;
            asm volatile("cp.async.cg.shared.global [%0], [%1], 16;"
                         :: "r"(sdst + (uint32_t)j * 8192u), "l"(src) : "memory");
        }
        asm volatile("cp.async.commit_group;" ::: "memory");
    };

    // A LDS byte base within a stage for this warp/lane (team half + warp rows)
    const uint32_t a_lds_off =
        (uint32_t)team * 32768u + (uint32_t)((warp_m * 4 * 4) * 32 + lid) * 16u;

    float acc[4][4][4];
    #pragma unroll
    for (int mt = 0; mt < 4; ++mt)
        #pragma unroll
        for (int nt = 0; nt < 4; ++nt)
            #pragma unroll
            for (int e = 0; e < 4; ++e) acc[mt][nt][e] = 0.0f;

    // B staging: 1 group per thread per super-iter (64 rows x 8 groups = 512)
    const int br = tid >> 3;        // B row in tile (0..63)
    const int bj = tid & 7;         // group within K-super-chunk (0..7)
    const int bg_base = (ntile * 64 + br) * 256 + bj;   // + si*8

    int4  bv;
    float bn;

    auto ldg_b = [&](int si) {
        int gidx = bg_base + si * 8;
        bv = __ldg(wq + gidx);
        bn = norm_f32 ? __ldg(wnf + gidx) : __half2float(__ldg(wnh + gidx));
    };
    auto sts_b = [&](int b) {
        char* bbuf = smem + SMEM_B + b * 16384 + (bj >> 2) * 8192;
        uint32_t o[8];
        dequant16(bv, bn, o);
        uint32_t off = (uint32_t)(br * 128 + (bj & 3) * 32);
        *reinterpret_cast<int4*>(bbuf + sw128(off)) =
            make_int4((int)o[0], (int)o[1], (int)o[2], (int)o[3]);
        *reinterpret_cast<int4*>(bbuf + sw128(off + 16)) =
            make_int4((int)o[4], (int)o[5], (int)o[6], (int)o[7]);
    };

    // ---- prologue ----
    ldg_b(0);
    cp_a(0, 0);
    cp_a(1, 1);
    sts_b(0);
    asm volatile("cp.async.wait_group 1;" ::: "memory");   // stage 0 ready
    __syncthreads();

    int s_cur = 0;   // (si) % 3
    int s_nxt = 2;   // (si+2) % 3

    #pragma unroll 1
    for (int si = 0; si < SITERS; ++si) {
        const int b = si & 1;
        if (si + 1 < SITERS) ldg_b(si + 1);

        const char* aslot = smem + SMEM_A + s_cur * 65536 + a_lds_off;
        const uint32_t bb = sb + SMEM_B + (uint32_t)b * 16384u + (uint32_t)team * 8192u;

        #pragma unroll
        for (int ks = 0; ks < 4; ++ks) {
            const uint32_t kb = (uint32_t)(ks * 32);   // 16 halves per k-step

            // A fragments for this ks: 4 x LDS.128 (mt = 0..3)
            uint4 af[4];
            #pragma unroll
            for (int mt = 0; mt < 4; ++mt)
                af[mt] = *reinterpret_cast<const uint4*>(
                    aslot + (mt * 4 + ks) * 32 * 16);

            uint32_t bf[2][4];
            #pragma unroll
            for (int p = 0; p < 2; ++p) {
                uint32_t addr = bb + sw128(brow[p] + kb);
                asm volatile(
                    "ldmatrix.sync.aligned.m8n8.x4.shared.b16 {%0,%1,%2,%3}, [%4];"
                    : "=r"(bf[p][0]), "=r"(bf[p][1]), "=r"(bf[p][2]), "=r"(bf[p][3])
                    : "r"(addr));
            }
            #pragma unroll
            for (int mt = 0; mt < 4; ++mt) {
                #pragma unroll
                for (int nt = 0; nt < 4; ++nt) {
                    uint32_t b0 = bf[nt >> 1][nt & 1];
                    uint32_t b1 = bf[nt >> 1][(nt & 1) + 2];
                    asm volatile(
                        "mma.sync.aligned.m16n8k16.row.col.f32.f16.f16.f32 "
                        "{%0,%1,%2,%3}, {%4,%5,%6,%7}, {%8,%9}, {%0,%1,%2,%3};"
                        : "+f"(acc[mt][nt][0]), "+f"(acc[mt][nt][1]),
                          "+f"(acc[mt][nt][2]), "+f"(acc[mt][nt][3])
                        : "r"(af[mt].x), "r"(af[mt].y),
                          "r"(af[mt].z), "r"(af[mt].w),
                          "r"(b0), "r"(b1));
                }
            }
        }

        if (si + 1 < SITERS) sts_b(b ^ 1);

        // Issue A copy for si+2; at the tail commit an EMPTY group so
        // wait_group 1 keeps counting correctly (no redundant copies).
        if (si + 2 < SITERS) cp_a(si + 2, s_nxt);
        else asm volatile("cp.async.commit_group;" ::: "memory");
        asm volatile("cp.async.wait_group 1;" ::: "memory");   // stage si+1 ready
        __syncthreads();

        s_cur = (s_cur == 2) ? 0 : s_cur + 1;
        s_nxt = (s_nxt == 2) ? 0 : s_nxt + 1;
    }

    // ---- drain the async pipe before reusing the A ring for the reduction ----
    asm volatile("cp.async.wait_group 0;" ::: "memory");
    __syncthreads();

    // ---- split-K reduction: team 1 -> smem -> team 0 adds ----
    // Reuse the A ring region. Per team-1 warp: 16 float4 chunks laid out
    // [chunk(16)][lane(32)] so loads are conflict-free.
    if (team == 1) {
        char* red = smem + SMEM_A + cwid * 8192 + lid * 16;
        #pragma unroll
        for (int mt = 0; mt < 4; ++mt)
            #pragma unroll
            for (int nt = 0; nt < 4; ++nt)
                *reinterpret_cast<float4*>(red + (mt * 4 + nt) * 512) =
                    make_float4(acc[mt][nt][0], acc[mt][nt][1],
                                acc[mt][nt][2], acc[mt][nt][3]);
    }
    __syncthreads();

    if (team == 0) {
        const char* red = smem + SMEM_A + cwid * 8192 + lid * 16;
        const int mbase = warp_m * 64;
        const int nbase = ntile * 64 + warp_n * 32;
        const int rq = lid >> 2;             // row within m16 (0..7)
        const int cq = (lid & 3) * 2;        // col within n8 (0,2,4,6)
        #pragma unroll
        for (int mt = 0; mt < 4; ++mt) {
            #pragma unroll
            for (int nt = 0; nt < 4; ++nt) {
                float4 r = *reinterpret_cast<const float4*>(red + (mt * 4 + nt) * 512);
                int m0 = mbase + mt * 16 + rq;
                int n0 = nbase + nt * 8 + cq;
                float2 bsv = __ldg(reinterpret_cast<const float2*>(bias + n0));
                float2 v0, v1;
                v0.x = acc[mt][nt][0] + r.x + bsv.x;
                v0.y = acc[mt][nt][1] + r.y + bsv.y;
                v1.x = acc[mt][nt][2] + r.z + bsv.x;
                v1.y = acc[mt][nt][3] + r.w + bsv.y;
                *reinterpret_cast<float2*>(out + (size_t)m0 * N + n0) = v0;
                *reinterpret_cast<float2*>(out + (size_t)(m0 + 8) * N + n0) = v1;
            }
        }
    }
}

// ---------------- launch ----------------

extern "C" void kernel_launch(void* const* d_in, const int* in_sizes, int n_in,
                              void* d_out, int out_size) {
    (void)in_sizes; (void)n_in; (void)out_size;
    const float* x    = (const float*)d_in[0];
    const int4*  wq   = (const int4*)d_in[1];    // [NUM_GROUPS] groups of 4 int32
    const void*  wn   = (const void*)d_in[2];    // [NUM_GROUPS] norms
    const float* bias = (const float*)d_in[3];
    float*       out  = (float*)d_out;

    cudaFuncSetAttribute(linear2bit_gemm,
                         cudaFuncAttributeMaxDynamicSharedMemorySize, SMEM_TOTAL);

    convert_x_frag<<<(M / 16) * (K / 16) * 32 / 256, 256>>>(x);
    linear2bit_gemm<<<N / 64, THREADS, SMEM_TOTAL>>>(wq, wn, bias, out);
}